// round 1
// baseline (speedup 1.0000x reference)
#include <cuda_runtime.h>
#include <math.h>

// ---------------- problem constants ----------------
#define Bc   4
#define Nc   50000
#define BNc  (Bc * Nc)
#define Tc   12
#define Hc   32
#define H2c  64
#define Rc   64

#define NRM     0.4204482076268573f   /* 32^-0.25 */
#define RATIO   0.125f                /* 64^-0.5  */
#define EPSP    1e-4f
#define EPS_LN  1e-5f

#define PB         98                 /* kv partial blocks per batch */
#define CHUNK      512                /* nodes per kv block          */
#define TJ         32                 /* node tile in kv inner loop  */
#define DEN_CHUNKS 196                /* ceil(Nc/256)                */

// ---------------- scratch (__device__ globals; no runtime alloc) ----------------
__device__ float    d_qp[Rc * Nc];        // per-node query features (b-independent)
__device__ float    d_fk[Rc * Nc];        // dd_k - diag_k
__device__ float    d_kp[Rc * Nc];        // key features
__device__ float    d_hnode[H2c * Nc];    // node_emb @ fc_w[:,32:64] + fc_b
__device__ float    d_h0[H2c * BNc];      // v = relu(xc @ fc_w + fc_b)
__device__ float    d_ie[Hc * BNc];       // input_emb (left half of xc)
__device__ unsigned d_keymax;             // encoded global max of dd_k
__device__ float    d_kv[Bc][Rc * H2c];
__device__ float    d_denv[Rc];
__device__ float    d_kvpart[Bc][PB][Rc * H2c];
__device__ float    d_denpart[Rc][DEN_CHUNKS];

// ---------------- init ----------------
__global__ void kInit() { d_keymax = 0u; }

// ---------------- Stage A: per-node (b-independent) ----------------
__global__ void __launch_bounds__(128) kA(
    const float* __restrict__ node_emb,
    const float* __restrict__ w1, const float* __restrict__ b1,
    const float* __restrict__ w2, const float* __restrict__ b2,
    const float* __restrict__ rm1,
    const float* __restrict__ fc_w, const float* __restrict__ fc_b)
{
    __shared__ float s_w1[Hc * Hc], s_w2[Hc * Hc], s_rm[Rc * Hc], s_fr[H2c * Hc];
    __shared__ float s_b1[Hc], s_b2[Hc], s_fb[H2c];
    int tid = threadIdx.x;
    for (int i = tid; i < Hc * Hc; i += 128) { s_w1[i] = w1[i]; s_w2[i] = w2[i]; }
    for (int i = tid; i < Rc * Hc; i += 128) s_rm[i] = rm1[i];
    for (int i = tid; i < H2c * Hc; i += 128) {
        int o = i / Hc, d = i % Hc;
        s_fr[i] = fc_w[o * H2c + Hc + d];      // right half (node part)
    }
    if (tid < Hc)  { s_b1[tid] = b1[tid]; s_b2[tid] = b2[tid]; }
    if (tid < H2c) s_fb[tid] = fc_b[tid];
    __syncthreads();

    int n = blockIdx.x * 128 + tid;
    float kmaxdd = -3.0e38f;

    if (n < Nc) {
        float nd[Hc];
        #pragma unroll
        for (int d = 0; d < Hc; d++) nd[d] = node_emb[n * Hc + d];

        float nv[Hc];

        // ---- queries: nv1 = node @ w1 + b1 ----
        #pragma unroll
        for (int h = 0; h < Hc; h++) {
            float a = s_b1[h];
            #pragma unroll
            for (int d = 0; d < Hc; d++) a += nd[d] * s_w1[h * Hc + d];
            nv[h] = a;
        }
        float diag = 0.f;
        #pragma unroll
        for (int h = 0; h < Hc; h++) diag += nv[h] * nv[h];
        diag *= 0.5f * NRM * NRM;

        float mx = -3.0e38f;
        for (int r = 0; r < Rc; r++) {
            float a = 0.f;
            #pragma unroll
            for (int h = 0; h < Hc; h++) a += nv[h] * s_rm[r * Hc + h];
            a *= NRM;
            mx = fmaxf(mx, a);
        }
        for (int r = 0; r < Rc; r++) {
            float a = 0.f;
            #pragma unroll
            for (int h = 0; h < Hc; h++) a += nv[h] * s_rm[r * Hc + h];
            a *= NRM;
            d_qp[r * Nc + n] = RATIO * (expf(a - diag - mx) + EPSP);
        }

        // ---- keys: nv2 = node @ w2 + b2 ----
        #pragma unroll
        for (int h = 0; h < Hc; h++) {
            float a = s_b2[h];
            #pragma unroll
            for (int d = 0; d < Hc; d++) a += nd[d] * s_w2[h * Hc + d];
            nv[h] = a;
        }
        float diagk = 0.f;
        #pragma unroll
        for (int h = 0; h < Hc; h++) diagk += nv[h] * nv[h];
        diagk *= 0.5f * NRM * NRM;

        for (int r = 0; r < Rc; r++) {
            float a = 0.f;
            #pragma unroll
            for (int h = 0; h < Hc; h++) a += nv[h] * s_rm[r * Hc + h];
            a *= NRM;
            d_fk[r * Nc + n] = a - diagk;
            kmaxdd = fmaxf(kmaxdd, a);
        }

        // ---- hnode = node @ fc_w[:,32:64] + fc_b ----
        for (int o = 0; o < H2c; o++) {
            float a = s_fb[o];
            #pragma unroll
            for (int d = 0; d < Hc; d++) a += nd[d] * s_fr[o * Hc + d];
            d_hnode[o * Nc + n] = a;
        }
    }

    // order-invariant (deterministic) global max
    #pragma unroll
    for (int off = 16; off; off >>= 1)
        kmaxdd = fmaxf(kmaxdd, __shfl_xor_sync(0xffffffffu, kmaxdd, off));
    if ((tid & 31) == 0) {
        unsigned bits = __float_as_uint(kmaxdd);
        unsigned enc = (bits & 0x80000000u) ? ~bits : (bits | 0x80000000u);
        atomicMax(&d_keymax, enc);
    }
}

// ---------------- Stage A3: kp = ratio*(exp(fk - M) + eps), den partials ----------------
__global__ void __launch_bounds__(256) kKP()
{
    int r = blockIdx.y;
    int n = blockIdx.x * 256 + threadIdx.x;
    unsigned enc = d_keymax;
    float M = (enc & 0x80000000u) ? __uint_as_float(enc ^ 0x80000000u)
                                  : __uint_as_float(~enc);
    float v = 0.f;
    if (n < Nc) {
        v = RATIO * (expf(d_fk[r * Nc + n] - M) + EPSP);
        d_kp[r * Nc + n] = v;
    }
    __shared__ float red[256];
    red[threadIdx.x] = v;
    __syncthreads();
    #pragma unroll
    for (int s = 128; s; s >>= 1) {
        if (threadIdx.x < s) red[threadIdx.x] += red[threadIdx.x + s];
        __syncthreads();
    }
    if (threadIdx.x == 0) d_denpart[r][blockIdx.x] = red[0];
}

// ---------------- Stage V: per (b,n): input_emb + v = relu(ie@fcwL + hnode) ----------------
__global__ void __launch_bounds__(128) kV(
    const float* __restrict__ x,
    const float* __restrict__ w_input, const float* __restrict__ b_input,
    const float* __restrict__ fc_w)
{
    __shared__ float s_wi[Hc * Tc], s_bi[Hc], s_fl[H2c * Hc];
    int tid = threadIdx.x;
    for (int i = tid; i < Hc * Tc; i += 128) s_wi[i] = w_input[i];
    for (int i = tid; i < H2c * Hc; i += 128) {
        int o = i / Hc, d = i % Hc;
        s_fl[i] = fc_w[o * H2c + d];          // left half (ie part)
    }
    if (tid < Hc) s_bi[tid] = b_input[tid];
    __syncthreads();

    int bn = blockIdx.x * 128 + tid;
    if (bn >= BNc) return;
    int n = bn % Nc;

    float xt[Tc];
    const float* xp = x + (size_t)bn * (Tc * 3);
    #pragma unroll
    for (int t = 0; t < Tc; t++) xt[t] = xp[t * 3];

    float ie[Hc];
    #pragma unroll
    for (int h = 0; h < Hc; h++) {
        float a = s_bi[h];
        #pragma unroll
        for (int t = 0; t < Tc; t++) a += xt[t] * s_wi[h * Tc + t];
        ie[h] = a;
        d_ie[h * BNc + bn] = a;
    }
    for (int o = 0; o < H2c; o++) {
        float a = d_hnode[o * Nc + n];
        #pragma unroll
        for (int d = 0; d < Hc; d++) a += ie[d] * s_fl[o * Hc + d];
        d_h0[o * BNc + bn] = fmaxf(a, 0.f);
    }
}

// ---------------- Stage B: kv partials (deterministic) ----------------
__global__ void __launch_bounds__(256) kB()
{
    int b = blockIdx.y, p = blockIdx.x;
    int n0 = p * CHUNK;
    int n1 = min(n0 + CHUNK, Nc);
    int tid = threadIdx.x;
    int r = tid & 63;
    int cg = tid >> 6;                  // c base = cg*16

    __shared__ float s_kp[TJ][Rc + 1];  // [j][r]
    __shared__ float s_v[TJ][H2c + 4];  // [j][c], stride 68 -> float4-aligned rows

    float acc[16];
    #pragma unroll
    for (int q = 0; q < 16; q++) acc[q] = 0.f;

    for (int jt = n0; jt < n1; jt += TJ) {
        int cnt = min(TJ, n1 - jt);
        for (int k = tid; k < Rc * TJ; k += 256) {
            int rr = k / TJ, j = k % TJ;
            s_kp[j][rr] = (j < cnt) ? d_kp[rr * Nc + jt + j] : 0.f;
        }
        for (int k = tid; k < H2c * TJ; k += 256) {
            int c = k / TJ, j = k % TJ;
            s_v[j][c] = (j < cnt) ? d_h0[c * BNc + b * Nc + jt + j] : 0.f;
        }
        __syncthreads();
        #pragma unroll 2
        for (int j = 0; j < TJ; j++) {
            float kpv = s_kp[j][r];
            const float4* vp = (const float4*)&s_v[j][cg * 16];
            #pragma unroll
            for (int q = 0; q < 4; q++) {
                float4 v4 = vp[q];
                acc[q * 4 + 0] += kpv * v4.x;
                acc[q * 4 + 1] += kpv * v4.y;
                acc[q * 4 + 2] += kpv * v4.z;
                acc[q * 4 + 3] += kpv * v4.w;
            }
        }
        __syncthreads();
    }
    float* dst = &d_kvpart[b][p][r * H2c + cg * 16];
    #pragma unroll
    for (int q = 0; q < 4; q++)
        ((float4*)dst)[q] = make_float4(acc[q * 4 + 0], acc[q * 4 + 1],
                                        acc[q * 4 + 2], acc[q * 4 + 3]);
}

// ---------------- Stage B2: reduce kv + den partials ----------------
__global__ void __launch_bounds__(256) kB2()
{
    int idx = blockIdx.x * 256 + threadIdx.x;
    if (idx < Bc * Rc * H2c) {
        int b = idx / (Rc * H2c), rc = idx % (Rc * H2c);
        float s = 0.f;
        for (int p = 0; p < PB; p++) s += d_kvpart[b][p][rc];
        d_kv[b][rc] = s;
    } else if (idx < Bc * Rc * H2c + Rc) {
        int r = idx - Bc * Rc * H2c;
        float s = 0.f;
        for (int k = 0; k < DEN_CHUNKS; k++) s += d_denpart[r][k];
        d_denv[r] = s;
    }
}

// ---------------- Stage C: num/den, residual, LN, output GEMM ----------------
__global__ void __launch_bounds__(128) kC(
    const float* __restrict__ node_emb,
    const float* __restrict__ ln_g, const float* __restrict__ ln_b,
    const float* __restrict__ w_reg, const float* __restrict__ b_reg,
    float* __restrict__ out)
{
    int b = blockIdx.y;
    __shared__ float s_kv[Rc * H2c];
    __shared__ float s_den[Rc], s_g[H2c], s_be[H2c], s_wr[12 * 128], s_br[12];
    int tid = threadIdx.x;
    for (int i = tid; i < Rc * H2c; i += 128) s_kv[i] = d_kv[b][i];
    for (int i = tid; i < 12 * 128; i += 128) s_wr[i] = w_reg[i];
    if (tid < Rc)  s_den[tid] = d_denv[tid];
    if (tid < H2c) { s_g[tid] = ln_g[tid]; s_be[tid] = ln_b[tid]; }
    if (tid < 12)  s_br[tid] = b_reg[tid];
    __syncthreads();

    int n = blockIdx.x * 128 + tid;
    if (n >= Nc) return;
    int bn = b * Nc + n;

    float qp[Rc];
    #pragma unroll
    for (int r = 0; r < Rc; r++) qp[r] = d_qp[r * Nc + n];

    float den = 0.f;
    #pragma unroll
    for (int r = 0; r < Rc; r++) den += qp[r] * s_den[r];

    float h[H2c];
    #pragma unroll
    for (int c = 0; c < H2c; c++) h[c] = 0.f;
    #pragma unroll
    for (int r = 0; r < Rc; r++) {
        float q = qp[r];
        const float4* kvp = (const float4*)(s_kv + r * H2c);
        #pragma unroll
        for (int c4 = 0; c4 < 16; c4++) {
            float4 v = kvp[c4];
            h[c4 * 4 + 0] += q * v.x;
            h[c4 * 4 + 1] += q * v.y;
            h[c4 * 4 + 2] += q * v.z;
            h[c4 * 4 + 3] += q * v.w;
        }
    }

    float inv = 1.f / den;
    float xc[H2c];
    #pragma unroll
    for (int d = 0; d < Hc; d++) xc[d] = d_ie[d * BNc + bn];
    #pragma unroll
    for (int d = 0; d < Hc; d++) xc[Hc + d] = node_emb[n * Hc + d];

    float mu = 0.f;
    #pragma unroll
    for (int c = 0; c < H2c; c++) { h[c] = h[c] * inv + xc[c]; mu += h[c]; }
    mu *= (1.f / H2c);
    float var = 0.f;
    #pragma unroll
    for (int c = 0; c < H2c; c++) { float d0 = h[c] - mu; var += d0 * d0; }
    var *= (1.f / H2c);
    float rstd = rsqrtf(var + EPS_LN);
    #pragma unroll
    for (int c = 0; c < H2c; c++)
        h[c] = fmaxf((h[c] - mu) * rstd * s_g[c] + s_be[c], 0.f);
    #pragma unroll
    for (int c = 0; c < H2c; c++) xc[c] = fmaxf(xc[c], 0.f);

    float* op = out + (size_t)bn * 12;
    #pragma unroll
    for (int o = 0; o < 12; o++) {
        float a = s_br[o];
        const float* w = s_wr + o * 128;
        #pragma unroll
        for (int c = 0; c < H2c; c++) a += xc[c] * w[c];
        #pragma unroll
        for (int c = 0; c < H2c; c++) a += h[c] * w[H2c + c];
        op[o] = a;
    }
}

// ---------------- launch ----------------
extern "C" void kernel_launch(void* const* d_in, const int* in_sizes, int n_in,
                              void* d_out, int out_size)
{
    (void)in_sizes; (void)n_in; (void)out_size;
    const float* x        = (const float*)d_in[0];
    const float* node_emb = (const float*)d_in[1];
    const float* w_input  = (const float*)d_in[4];
    const float* b_input  = (const float*)d_in[5];
    const float* w1       = (const float*)d_in[6];
    const float* b1       = (const float*)d_in[7];
    const float* w2       = (const float*)d_in[8];
    const float* b2       = (const float*)d_in[9];
    const float* fc_w     = (const float*)d_in[14];
    const float* fc_b     = (const float*)d_in[15];
    const float* ln_g     = (const float*)d_in[18];
    const float* ln_b     = (const float*)d_in[19];
    const float* w_reg    = (const float*)d_in[22];
    const float* b_reg    = (const float*)d_in[23];
    const float* rm1      = (const float*)d_in[24];
    float* out = (float*)d_out;

    kInit<<<1, 1>>>();
    kA<<<(Nc + 127) / 128, 128>>>(node_emb, w1, b1, w2, b2, rm1, fc_w, fc_b);
    kKP<<<dim3(DEN_CHUNKS, Rc), 256>>>();
    kV<<<(BNc + 127) / 128, 128>>>(x, w_input, b_input, fc_w);
    kB<<<dim3(PB, Bc), 256>>>();
    kB2<<<(Bc * Rc * H2c + Rc + 255) / 256, 256>>>();
    kC<<<dim3((Nc + 127) / 128, Bc), 128>>>(node_emb, ln_g, ln_b, w_reg, b_reg, out);
}

// round 3
// speedup vs baseline: 1.0915x; 1.0915x over previous
#include <cuda_runtime.h>
#include <math.h>

// ---------------- problem constants ----------------
#define Bc   4
#define Nc   50000
#define BNc  (Bc * Nc)
#define Tc   12
#define Hc   32
#define H2c  64
#define Rc   64

#define NRM     0.4204482076268573f   /* 32^-0.25 */
#define RATIO   0.125f                /* 64^-0.5  */
#define EPSP    1e-4f
#define EPS_LN  1e-5f

#define PB         98                 /* kv partial blocks per batch */
#define CHUNK      512                /* nodes per kv block          */
#define TJ         32                 /* node tile in kv inner loop  */
#define DEN_CHUNKS 196                /* ceil(Nc/256)                */

// ---------------- scratch ----------------
__device__ float    d_qp[Rc * Nc];
__device__ float    d_fk[Rc * Nc];
__device__ float    d_kp[Rc * Nc];
__device__ float    d_hnode[H2c * Nc];
__device__ float    d_neT[Hc * Nc];       // node_emb transposed [d][n]
__device__ float    d_h0[H2c * BNc];
__device__ float    d_ie[Hc * BNc];
__device__ unsigned d_keymax;
__device__ float    d_kv[Bc][Rc * H2c];
__device__ float    d_denv[Rc];
__device__ float    d_kvpart[Bc][PB][Rc * H2c];
__device__ float    d_denpart[Rc][DEN_CHUNKS];

__global__ void kInit() { d_keymax = 0u; }

// ---------------- Stage A: per-node (b-independent), round-1 structure ----------------
__global__ void __launch_bounds__(128) kA(
    const float* __restrict__ node_emb,
    const float* __restrict__ w1, const float* __restrict__ b1,
    const float* __restrict__ w2, const float* __restrict__ b2,
    const float* __restrict__ rm1,
    const float* __restrict__ fc_w, const float* __restrict__ fc_b)
{
    __shared__ float s_w1[Hc * Hc], s_w2[Hc * Hc], s_rm[Rc * Hc], s_fr[H2c * Hc];
    __shared__ float s_b1[Hc], s_b2[Hc], s_fb[H2c];
    int tid = threadIdx.x;
    for (int i = tid; i < Hc * Hc; i += 128) { s_w1[i] = w1[i]; s_w2[i] = w2[i]; }
    for (int i = tid; i < Rc * Hc; i += 128) s_rm[i] = rm1[i];
    for (int i = tid; i < H2c * Hc; i += 128) {
        int o = i / Hc, d = i % Hc;
        s_fr[i] = fc_w[o * H2c + Hc + d];      // right half (node part)
    }
    if (tid < Hc)  { s_b1[tid] = b1[tid]; s_b2[tid] = b2[tid]; }
    if (tid < H2c) s_fb[tid] = fc_b[tid];
    __syncthreads();

    int n = blockIdx.x * 128 + tid;
    float kmaxdd = -3.0e38f;

    if (n < Nc) {
        float nd[Hc];
        #pragma unroll
        for (int d = 0; d < Hc; d++) nd[d] = node_emb[n * Hc + d];
        #pragma unroll
        for (int d = 0; d < Hc; d++) d_neT[d * Nc + n] = nd[d];

        float nv[Hc];

        // ---- queries: nv1 = node @ w1 + b1 ----
        #pragma unroll
        for (int h = 0; h < Hc; h++) {
            float a = s_b1[h];
            #pragma unroll
            for (int d = 0; d < Hc; d++) a += nd[d] * s_w1[h * Hc + d];
            nv[h] = a;
        }
        float diag = 0.f;
        #pragma unroll
        for (int h = 0; h < Hc; h++) diag += nv[h] * nv[h];
        diag *= 0.5f * NRM * NRM;

        float mx = -3.0e38f;
        for (int r = 0; r < Rc; r++) {
            float a = 0.f;
            #pragma unroll
            for (int h = 0; h < Hc; h++) a += nv[h] * s_rm[r * Hc + h];
            a *= NRM;
            mx = fmaxf(mx, a);
        }
        for (int r = 0; r < Rc; r++) {
            float a = 0.f;
            #pragma unroll
            for (int h = 0; h < Hc; h++) a += nv[h] * s_rm[r * Hc + h];
            a *= NRM;
            d_qp[r * Nc + n] = RATIO * (expf(a - diag - mx) + EPSP);
        }

        // ---- keys: nv2 = node @ w2 + b2 ----
        #pragma unroll
        for (int h = 0; h < Hc; h++) {
            float a = s_b2[h];
            #pragma unroll
            for (int d = 0; d < Hc; d++) a += nd[d] * s_w2[h * Hc + d];
            nv[h] = a;
        }
        float diagk = 0.f;
        #pragma unroll
        for (int h = 0; h < Hc; h++) diagk += nv[h] * nv[h];
        diagk *= 0.5f * NRM * NRM;

        for (int r = 0; r < Rc; r++) {
            float a = 0.f;
            #pragma unroll
            for (int h = 0; h < Hc; h++) a += nv[h] * s_rm[r * Hc + h];
            a *= NRM;
            d_fk[r * Nc + n] = a - diagk;
            kmaxdd = fmaxf(kmaxdd, a);
        }

        // ---- hnode = node @ fc_w[:,32:64] + fc_b ----
        for (int o = 0; o < H2c; o++) {
            float a = s_fb[o];
            #pragma unroll
            for (int d = 0; d < Hc; d++) a += nd[d] * s_fr[o * Hc + d];
            d_hnode[o * Nc + n] = a;
        }
    }

    // order-invariant (deterministic) global max
    #pragma unroll
    for (int off = 16; off; off >>= 1)
        kmaxdd = fmaxf(kmaxdd, __shfl_xor_sync(0xffffffffu, kmaxdd, off));
    if ((tid & 31) == 0) {
        unsigned bits = __float_as_uint(kmaxdd);
        unsigned enc = (bits & 0x80000000u) ? ~bits : (bits | 0x80000000u);
        atomicMax(&d_keymax, enc);
    }
}

// ---------------- kp = ratio*(exp(fk - M) + eps), den partials ----------------
__global__ void __launch_bounds__(256) kKP()
{
    int r = blockIdx.y;
    int n = blockIdx.x * 256 + threadIdx.x;
    unsigned enc = d_keymax;
    float M = (enc & 0x80000000u) ? __uint_as_float(enc ^ 0x80000000u)
                                  : __uint_as_float(~enc);
    float v = 0.f;
    if (n < Nc) {
        v = RATIO * (expf(d_fk[r * Nc + n] - M) + EPSP);
        d_kp[r * Nc + n] = v;
    }
    __shared__ float red[256];
    red[threadIdx.x] = v;
    __syncthreads();
    #pragma unroll
    for (int s = 128; s; s >>= 1) {
        if (threadIdx.x < s) red[threadIdx.x] += red[threadIdx.x + s];
        __syncthreads();
    }
    if (threadIdx.x == 0) d_denpart[r][blockIdx.x] = red[0];
}

// ---------------- Stage V: input_emb + v = relu(ie@fcwL + hnode) ----------------
__global__ void __launch_bounds__(128) kV(
    const float* __restrict__ x,
    const float* __restrict__ w_input, const float* __restrict__ b_input,
    const float* __restrict__ fc_w)
{
    __shared__ float s_wi[Hc * Tc], s_bi[Hc], s_fl[H2c * Hc];
    __shared__ float s_x[128 * 37];
    int tid = threadIdx.x;
    for (int i = tid; i < Hc * Tc; i += 128) s_wi[i] = w_input[i];
    for (int i = tid; i < H2c * Hc; i += 128) {
        int o = i / Hc, d = i % Hc;
        s_fl[i] = fc_w[o * H2c + d];          // left half (ie part)
    }
    if (tid < Hc) s_bi[tid] = b_input[tid];

    // coalesced float4 staging of x (rows of 36 floats, padded stride 37)
    {
        size_t base = (size_t)blockIdx.x * (128 * 36);
        size_t total = (size_t)BNc * 36;
        int rem = (int)min((size_t)(128 * 36), total - base);
        const float4* xp4 = (const float4*)(x + base);
        int nv4 = rem >> 2;
        for (int i = tid; i < nv4; i += 128) {
            float4 v = xp4[i];
            int e = i * 4;
            int r0 = e / 36, c0 = e - r0 * 36;
            float vv0 = v.x, vv1 = v.y, vv2 = v.z, vv3 = v.w;
            int r1 = r0, c1 = c0 + 1; if (c1 >= 36) { r1++; c1 -= 36; }
            int r2 = r0, c2 = c0 + 2; if (c2 >= 36) { r2++; c2 -= 36; }
            int r3 = r0, c3 = c0 + 3; if (c3 >= 36) { r3++; c3 -= 36; }
            s_x[r0 * 37 + c0] = vv0;
            s_x[r1 * 37 + c1] = vv1;
            s_x[r2 * 37 + c2] = vv2;
            s_x[r3 * 37 + c3] = vv3;
        }
    }
    __syncthreads();

    int bn = blockIdx.x * 128 + tid;
    if (bn >= BNc) return;
    int n = bn % Nc;

    float xt[Tc];
    #pragma unroll
    for (int t = 0; t < Tc; t++) xt[t] = s_x[tid * 37 + t * 3];

    float ie[Hc];
    #pragma unroll
    for (int h = 0; h < Hc; h++) {
        float a = s_bi[h];
        #pragma unroll
        for (int t = 0; t < Tc; t++) a += xt[t] * s_wi[h * Tc + t];
        ie[h] = a;
        d_ie[h * BNc + bn] = a;
    }
    for (int o = 0; o < H2c; o++) {
        float a = d_hnode[o * Nc + n];
        #pragma unroll
        for (int d = 0; d < Hc; d++) a += ie[d] * s_fl[o * Hc + d];
        d_h0[o * BNc + bn] = fmaxf(a, 0.f);
    }
}

// ---------------- Stage B: kv partials (round-1 structure) ----------------
__global__ void __launch_bounds__(256) kB()
{
    int b = blockIdx.y, p = blockIdx.x;
    int n0 = p * CHUNK;
    int n1 = min(n0 + CHUNK, Nc);
    int tid = threadIdx.x;
    int r = tid & 63;
    int cg = tid >> 6;                  // c base = cg*16

    __shared__ float s_kp[TJ][Rc + 1];  // [j][r]
    __shared__ float s_v[TJ][H2c + 4];  // [j][c], float4-aligned rows

    float acc[16];
    #pragma unroll
    for (int q = 0; q < 16; q++) acc[q] = 0.f;

    for (int jt = n0; jt < n1; jt += TJ) {
        int cnt = min(TJ, n1 - jt);
        for (int k = tid; k < Rc * TJ; k += 256) {
            int rr = k / TJ, j = k % TJ;
            s_kp[j][rr] = (j < cnt) ? d_kp[rr * Nc + jt + j] : 0.f;
        }
        for (int k = tid; k < H2c * TJ; k += 256) {
            int c = k / TJ, j = k % TJ;
            s_v[j][c] = (j < cnt) ? d_h0[c * BNc + b * Nc + jt + j] : 0.f;
        }
        __syncthreads();
        #pragma unroll 2
        for (int j = 0; j < TJ; j++) {
            float kpv = s_kp[j][r];
            const float4* vp = (const float4*)&s_v[j][cg * 16];
            #pragma unroll
            for (int q = 0; q < 4; q++) {
                float4 v4 = vp[q];
                acc[q * 4 + 0] += kpv * v4.x;
                acc[q * 4 + 1] += kpv * v4.y;
                acc[q * 4 + 2] += kpv * v4.z;
                acc[q * 4 + 3] += kpv * v4.w;
            }
        }
        __syncthreads();
    }
    float* dst = &d_kvpart[b][p][r * H2c + cg * 16];
    #pragma unroll
    for (int q = 0; q < 4; q++)
        ((float4*)dst)[q] = make_float4(acc[q * 4 + 0], acc[q * 4 + 1],
                                        acc[q * 4 + 2], acc[q * 4 + 3]);
}

// ---------------- reduce kv + den partials ----------------
__global__ void __launch_bounds__(256) kB2()
{
    int idx = blockIdx.x * 256 + threadIdx.x;
    if (idx < Bc * Rc * H2c) {
        int b = idx / (Rc * H2c), rc = idx % (Rc * H2c);
        float s = 0.f;
        for (int p = 0; p < PB; p++) s += d_kvpart[b][p][rc];
        d_kv[b][rc] = s;
    } else if (idx < Bc * Rc * H2c + Rc) {
        int r = idx - Bc * Rc * H2c;
        float s = 0.f;
        for (int k = 0; k < DEN_CHUNKS; k++) s += d_denpart[r][k];
        d_denv[r] = s;
    }
}

// ---------------- Stage C: streaming qp, fused residual/LN/out GEMM ----------------
__global__ void __launch_bounds__(128) kC(
    const float* __restrict__ ln_g, const float* __restrict__ ln_b,
    const float* __restrict__ w_reg, const float* __restrict__ b_reg,
    float* __restrict__ out)
{
    int b = blockIdx.y;
    __shared__ float4 s_kv4[Rc * 16];          // kv rows as float4
    __shared__ float4 s_wr4[12 * 32];          // w_reg rows as float4
    __shared__ float  s_den[Rc], s_g[H2c], s_be[H2c], s_br[12];
    int tid = threadIdx.x;
    {
        const float4* kvsrc = (const float4*)&d_kv[b][0];
        for (int i = tid; i < Rc * 16; i += 128) s_kv4[i] = kvsrc[i];
        const float4* wrsrc = (const float4*)w_reg;
        for (int i = tid; i < 12 * 32; i += 128) s_wr4[i] = wrsrc[i];
    }
    if (tid < Rc)  s_den[tid] = d_denv[tid];
    if (tid < H2c) { s_g[tid] = ln_g[tid]; s_be[tid] = ln_b[tid]; }
    if (tid < 12)  s_br[tid] = b_reg[tid];
    __syncthreads();

    int n = blockIdx.x * 128 + tid;
    if (n >= Nc) return;
    int bn = b * Nc + n;

    float h[H2c];
    #pragma unroll
    for (int c = 0; c < H2c; c++) h[c] = 0.f;
    float den = 0.f;

    #pragma unroll 4
    for (int r = 0; r < Rc; r++) {
        float q = d_qp[r * Nc + n];
        den += q * s_den[r];
        const float4* kvp = &s_kv4[r * 16];
        #pragma unroll
        for (int c4 = 0; c4 < 16; c4++) {
            float4 v = kvp[c4];
            h[c4 * 4 + 0] += q * v.x;
            h[c4 * 4 + 1] += q * v.y;
            h[c4 * 4 + 2] += q * v.z;
            h[c4 * 4 + 3] += q * v.w;
        }
    }

    float inv = 1.f / den;
    float outr[12];
    #pragma unroll
    for (int o = 0; o < 12; o++) outr[o] = s_br[o];

    float mu = 0.f;
    // ie part (c = 0..31): residual add + relu(x0) GEMM, no xc array kept
    #pragma unroll
    for (int c4 = 0; c4 < 8; c4++) {
        float xv0, xv1, xv2, xv3;
        {
            float v0 = d_ie[(c4 * 4 + 0) * BNc + bn];
            float v1 = d_ie[(c4 * 4 + 1) * BNc + bn];
            float v2 = d_ie[(c4 * 4 + 2) * BNc + bn];
            float v3 = d_ie[(c4 * 4 + 3) * BNc + bn];
            h[c4 * 4 + 0] = h[c4 * 4 + 0] * inv + v0; mu += h[c4 * 4 + 0];
            h[c4 * 4 + 1] = h[c4 * 4 + 1] * inv + v1; mu += h[c4 * 4 + 1];
            h[c4 * 4 + 2] = h[c4 * 4 + 2] * inv + v2; mu += h[c4 * 4 + 2];
            h[c4 * 4 + 3] = h[c4 * 4 + 3] * inv + v3; mu += h[c4 * 4 + 3];
            xv0 = fmaxf(v0, 0.f); xv1 = fmaxf(v1, 0.f);
            xv2 = fmaxf(v2, 0.f); xv3 = fmaxf(v3, 0.f);
        }
        #pragma unroll
        for (int o = 0; o < 12; o++) {
            float4 w = s_wr4[o * 32 + c4];
            outr[o] += xv0 * w.x + xv1 * w.y + xv2 * w.z + xv3 * w.w;
        }
    }
    // node part (c = 32..63)
    #pragma unroll
    for (int c4 = 8; c4 < 16; c4++) {
        float xv0, xv1, xv2, xv3;
        {
            float v0 = d_neT[(c4 * 4 + 0 - Hc) * Nc + n];
            float v1 = d_neT[(c4 * 4 + 1 - Hc) * Nc + n];
            float v2 = d_neT[(c4 * 4 + 2 - Hc) * Nc + n];
            float v3 = d_neT[(c4 * 4 + 3 - Hc) * Nc + n];
            h[c4 * 4 + 0] = h[c4 * 4 + 0] * inv + v0; mu += h[c4 * 4 + 0];
            h[c4 * 4 + 1] = h[c4 * 4 + 1] * inv + v1; mu += h[c4 * 4 + 1];
            h[c4 * 4 + 2] = h[c4 * 4 + 2] * inv + v2; mu += h[c4 * 4 + 2];
            h[c4 * 4 + 3] = h[c4 * 4 + 3] * inv + v3; mu += h[c4 * 4 + 3];
            xv0 = fmaxf(v0, 0.f); xv1 = fmaxf(v1, 0.f);
            xv2 = fmaxf(v2, 0.f); xv3 = fmaxf(v3, 0.f);
        }
        #pragma unroll
        for (int o = 0; o < 12; o++) {
            float4 w = s_wr4[o * 32 + c4];
            outr[o] += xv0 * w.x + xv1 * w.y + xv2 * w.z + xv3 * w.w;
        }
    }

    mu *= (1.f / H2c);
    float var = 0.f;
    #pragma unroll
    for (int c = 0; c < H2c; c++) { float d0 = h[c] - mu; var += d0 * d0; }
    var *= (1.f / H2c);
    float rstd = rsqrtf(var + EPS_LN);
    #pragma unroll
    for (int c = 0; c < H2c; c++)
        h[c] = fmaxf((h[c] - mu) * rstd * s_g[c] + s_be[c], 0.f);

    #pragma unroll
    for (int c4 = 0; c4 < 16; c4++) {
        float h0 = h[c4 * 4 + 0], h1 = h[c4 * 4 + 1];
        float h2 = h[c4 * 4 + 2], h3 = h[c4 * 4 + 3];
        #pragma unroll
        for (int o = 0; o < 12; o++) {
            float4 w = s_wr4[o * 32 + 16 + c4];
            outr[o] += h0 * w.x + h1 * w.y + h2 * w.z + h3 * w.w;
        }
    }

    float* op = out + (size_t)bn * 12;
    #pragma unroll
    for (int o = 0; o < 12; o++) op[o] = outr[o];
}

// ---------------- launch ----------------
extern "C" void kernel_launch(void* const* d_in, const int* in_sizes, int n_in,
                              void* d_out, int out_size)
{
    (void)in_sizes; (void)n_in; (void)out_size;
    const float* x        = (const float*)d_in[0];
    const float* node_emb = (const float*)d_in[1];
    const float* w_input  = (const float*)d_in[4];
    const float* b_input  = (const float*)d_in[5];
    const float* w1       = (const float*)d_in[6];
    const float* b1       = (const float*)d_in[7];
    const float* w2       = (const float*)d_in[8];
    const float* b2       = (const float*)d_in[9];
    const float* fc_w     = (const float*)d_in[14];
    const float* fc_b     = (const float*)d_in[15];
    const float* ln_g     = (const float*)d_in[18];
    const float* ln_b     = (const float*)d_in[19];
    const float* w_reg    = (const float*)d_in[22];
    const float* b_reg    = (const float*)d_in[23];
    const float* rm1      = (const float*)d_in[24];
    float* out = (float*)d_out;

    kInit<<<1, 1>>>();
    kA<<<(Nc + 127) / 128, 128>>>(node_emb, w1, b1, w2, b2, rm1, fc_w, fc_b);
    kKP<<<dim3(DEN_CHUNKS, Rc), 256>>>();
    kV<<<(BNc + 127) / 128, 128>>>(x, w_input, b_input, fc_w);
    kB<<<dim3(PB, Bc), 256>>>();
    kB2<<<(Bc * Rc * H2c + Rc + 255) / 256, 256>>>();
    kC<<<dim3((Nc + 127) / 128, Bc), 128>>>(ln_g, ln_b, w_reg, b_reg, out);
}